// round 4
// baseline (speedup 1.0000x reference)
#include <cuda_runtime.h>
#include <cuda_bf16.h>

#define N_STREAMS 4
#define C_DIM 4096
#define ROW_ELEMS (N_STREAMS * C_DIM)
#define THREADS 512
#define COLS_PER_THREAD 8   // 512 * 8 = 4096
#define EPS_F 1e-6f

__global__ __launch_bounds__(THREADS, 2)
void mhc_fused_kernel(const float* __restrict__ x,
                      const float* __restrict__ w,
                      const float* __restrict__ Hpre,
                      const float* __restrict__ Hpost,
                      const float* __restrict__ Hres,
                      float* __restrict__ out,
                      int B)
{
    const int t = threadIdx.x;
    const int warp = t >> 5;
    const int lane = t & 31;
    const int c0 = t * COLS_PER_THREAD;

    __shared__ float sM[16];
    __shared__ float sPre[4];
    __shared__ float sPost[4];
    __shared__ float sRed[16];
    __shared__ float sInvRms;

    // ---- once per CTA: sigmoids + Sinkhorn on the 4x4 ----
    if (t == 0) {
        float P[16];
#pragma unroll
        for (int i = 0; i < 16; ++i) P[i] = expf(Hres[i]);
#pragma unroll
        for (int it = 0; it < 3; ++it) {
#pragma unroll
            for (int r = 0; r < 4; ++r) {
                float s = P[r*4+0] + P[r*4+1] + P[r*4+2] + P[r*4+3] + EPS_F;
                float inv = 1.0f / s;
#pragma unroll
                for (int cc = 0; cc < 4; ++cc) P[r*4+cc] *= inv;
            }
#pragma unroll
            for (int cc = 0; cc < 4; ++cc) {
                float s = P[0*4+cc] + P[1*4+cc] + P[2*4+cc] + P[3*4+cc] + EPS_F;
                float inv = 1.0f / s;
#pragma unroll
                for (int r = 0; r < 4; ++r) P[r*4+cc] *= inv;
            }
        }
#pragma unroll
        for (int i = 0; i < 16; ++i) sM[i] = P[i];
#pragma unroll
        for (int n = 0; n < 4; ++n) {
            sPre[n]  = 1.0f / (1.0f + expf(-Hpre[n]));
            sPost[n] = 2.0f / (1.0f + expf(-Hpost[n]));
        }
    }
    __syncthreads();

    // ---- hoisted thread-local pointers, strided by grid step ----
    const size_t step = (size_t)gridDim.x * ROW_ELEMS;
    const float* xp = x   + (size_t)blockIdx.x * ROW_ELEMS + c0;
    float*       op = out + (size_t)blockIdx.x * ROW_ELEMS + c0;
    const float4* pw = reinterpret_cast<const float4*>(w + c0);

    // ---- persistent loop over batch rows ----
    for (int b = blockIdx.x; b < B; b += gridDim.x, xp += step, op += step) {
        // 8 independent LDG.128 up front (max MLP)
        float xv[N_STREAMS][COLS_PER_THREAD];
#pragma unroll
        for (int n = 0; n < N_STREAMS; ++n) {
            const float4* p = reinterpret_cast<const float4*>(xp + n * C_DIM);
            float4 a = p[0];
            float4 c = p[1];
            xv[n][0] = a.x; xv[n][1] = a.y; xv[n][2] = a.z; xv[n][3] = a.w;
            xv[n][4] = c.x; xv[n][5] = c.y; xv[n][6] = c.z; xv[n][7] = c.w;
        }

        // weighted aggregation over streams (uniform scalars from shared)
        float agg[COLS_PER_THREAD];
#pragma unroll
        for (int j = 0; j < COLS_PER_THREAD; ++j) {
            float a = sPre[0] * xv[0][j];
            a = fmaf(sPre[1], xv[1][j], a);
            a = fmaf(sPre[2], xv[2][j], a);
            a = fmaf(sPre[3], xv[3][j], a);
            agg[j] = a;
        }

        // sum-of-squares reduction over C
        float ss = 0.0f;
#pragma unroll
        for (int j = 0; j < COLS_PER_THREAD; ++j) ss = fmaf(agg[j], agg[j], ss);
#pragma unroll
        for (int off = 16; off > 0; off >>= 1)
            ss += __shfl_xor_sync(0xFFFFFFFFu, ss, off);
        if (lane == 0) sRed[warp] = ss;
        __syncthreads();
        if (warp == 0) {
            float v = (lane < (THREADS / 32)) ? sRed[lane] : 0.0f;
#pragma unroll
            for (int off = 8; off > 0; off >>= 1)
                v += __shfl_xor_sync(0xFFFFFFFFu, v, off);
            if (lane == 0) {
                float mean = v * (1.0f / (float)C_DIM);
                sInvRms = 1.0f / sqrtf(mean + EPS_F);
            }
        }
        __syncthreads();
        const float invRms = sInvRms;
        // No trailing barrier needed: sInvRms is only rewritten by warp0 after
        // the NEXT iteration's first barrier, which can't release until every
        // warp has already consumed this iteration's value; sRed writes are to
        // disjoint slots re-filled only before that same barrier.

        // y_norm (exact bf16 round-trip), folded into agg in place.
        // w is 16KB, L1-resident after first iteration of the persistent loop.
        {
            float4 a = pw[0];
            float4 c = pw[1];
            float wv[COLS_PER_THREAD] = {a.x, a.y, a.z, a.w, c.x, c.y, c.z, c.w};
#pragma unroll
            for (int j = 0; j < COLS_PER_THREAD; ++j) {
                float y = agg[j] * invRms * wv[j];
                agg[j] = __bfloat162float(__float2bfloat16(y));
            }
        }

        // mix + scaled-norm add, store (M/hpost broadcast from shared)
#pragma unroll
        for (int n = 0; n < N_STREAMS; ++n) {
            const float m0 = sM[n*4+0], m1 = sM[n*4+1], m2 = sM[n*4+2], m3 = sM[n*4+3];
            const float hp = sPost[n];
            float o[COLS_PER_THREAD];
#pragma unroll
            for (int j = 0; j < COLS_PER_THREAD; ++j) {
                float v = m0 * xv[0][j];
                v = fmaf(m1, xv[1][j], v);
                v = fmaf(m2, xv[2][j], v);
                v = fmaf(m3, xv[3][j], v);
                o[j] = fmaf(hp, agg[j], v);
            }
            float4* po = reinterpret_cast<float4*>(op + n * C_DIM);
            po[0] = make_float4(o[0], o[1], o[2], o[3]);
            po[1] = make_float4(o[4], o[5], o[6], o[7]);
        }
    }
}

extern "C" void kernel_launch(void* const* d_in, const int* in_sizes, int n_in,
                              void* d_out, int out_size)
{
    const float* x     = (const float*)d_in[0];
    const float* w     = (const float*)d_in[1];
    const float* Hpre  = (const float*)d_in[2];
    const float* Hpost = (const float*)d_in[3];
    const float* Hres  = (const float*)d_in[4];
    float* out = (float*)d_out;

    const int B = in_sizes[0] / ROW_ELEMS;

    int sm_count = 0;
    cudaDeviceGetAttribute(&sm_count, cudaDevAttrMultiProcessorCount, 0);
    if (sm_count <= 0) sm_count = 148;
    int grid = sm_count * 2;            // occ=2 persistent CTAs
    if (grid > B) grid = B;

    mhc_fused_kernel<<<grid, THREADS>>>(x, w, Hpre, Hpost, Hres, out, B);
}